// round 15
// baseline (speedup 1.0000x reference)
#include <cuda_runtime.h>

// Stochastic LIF neuron scan — R10.
// Inputs (metadata order): x [B,T,N] f32, noise [B,T,N] f32, unif [B,T,N] f32.
// Output: spikes [B,T,N] f32.
//
// Bit-exact step per (b,n):
//   u = 0.5*u + x_t        (separate mul+add, NO fma)
//   u = u - noise_t
//   q = ((u - 1) + 0.4) / 0.8   (IEEE div; clip elided — unif ∈ [0,1))
//   o = (unif_t < q);  u = o ? 0 : u
//
// R10 = R9's per-thread schedule (2 float4 tiles, ~64 regs) at block 1024,
// __launch_bounds__(1024, 1): ONE CTA per SM, still 32 warps/SM, full 64K RF.
// Terminal point of the measured gradient (fewer co-resident CTAs at constant
// warps -> higher DRAM%): 4 CTA 84.4% -> 2 CTA 84.9% -> 1 CTA (this).

#define B_DIM 32
#define T_DIM 16
#define N_DIM 65536
#define N4    (N_DIM / 4)     // 16384 float4 per (b,t) row
#define HALF  (N4 / 2)        // 8192: second tile offset within a row

__device__ __forceinline__ void lif_lane(float& u, float xv, float nv, float rv,
                                         float& ov)
{
    float un = __fadd_rn(__fmul_rn(0.5f, u), xv);
    un = __fsub_rn(un, nv);
    float v = __fsub_rn(un, 1.0f);
    float q = __fdiv_rn(__fadd_rn(v, 0.4f), 0.8f);
    bool  s = (rv < q);
    ov = s ? 1.0f : 0.0f;
    u  = s ? 0.0f : un;
}

__global__ __launch_bounds__(1024, 1)
void neuron_scan_kernel(const float4* __restrict__ x,
                        const float4* __restrict__ noise,
                        const float4* __restrict__ unif,
                        float4* __restrict__ out)
{
    int tid = blockIdx.x * blockDim.x + threadIdx.x;   // 0 .. B*HALF-1 (grid exact)

    int b   = tid >> 13;            // tid / HALF
    int off = tid & (HALF - 1);     // tid % HALF

    // two float4 tiles per thread: columns off and off+HALF of each row
    int idxA = b * (T_DIM * N4) + off;
    int idxB = idxA + HALF;

    float a0 = 0.0f, a1 = 0.0f, a2 = 0.0f, a3 = 0.0f;
    float b0 = 0.0f, b1 = 0.0f, b2 = 0.0f, b3 = 0.0f;

    #pragma unroll 4
    for (int t = 0; t < T_DIM; ++t) {
        float4 xa = x[idxA];
        float4 xb = x[idxB];
        float4 na = noise[idxA];
        float4 nb = noise[idxB];
        float4 ra = unif[idxA];
        float4 rb = unif[idxB];

        float4 oa, ob;
        lif_lane(a0, xa.x, na.x, ra.x, oa.x);
        lif_lane(a1, xa.y, na.y, ra.y, oa.y);
        lif_lane(a2, xa.z, na.z, ra.z, oa.z);
        lif_lane(a3, xa.w, na.w, ra.w, oa.w);

        lif_lane(b0, xb.x, nb.x, rb.x, ob.x);
        lif_lane(b1, xb.y, nb.y, rb.y, ob.y);
        lif_lane(b2, xb.z, nb.z, rb.z, ob.z);
        lif_lane(b3, xb.w, nb.w, rb.w, ob.w);

        out[idxA] = oa;
        out[idxB] = ob;

        idxA += N4;
        idxB += N4;
    }
}

extern "C" void kernel_launch(void* const* d_in, const int* in_sizes, int n_in,
                              void* d_out, int out_size)
{
    const float4* x     = (const float4*)d_in[0];
    const float4* noise = (const float4*)d_in[1];
    const float4* unif  = (const float4*)d_in[2];
    float4* out         = (float4*)d_out;

    const int total_threads = B_DIM * HALF;        // 262144
    const int block = 1024;
    const int grid  = total_threads / block;       // 256, exact

    neuron_scan_kernel<<<grid, block>>>(x, noise, unif, out);
}